// round 16
// baseline (speedup 1.0000x reference)
#include <cuda_runtime.h>
#include <cuda_fp16.h>
#include <mma.h>
#include <math.h>

using namespace nvcuda;

// Problem constants
#define NB    8
#define C     528
#define T     16
#define HH    32
#define WW    32
#define R     1024
#define OUTB  8
#define SR    2
#define SCALE (1.0f/16.0f)

#define NJ     128           // layer-1 width
#define NPX    (NB*HH*WW)    // 8192 pixels
#define MAXSUP 144

// NHWC feature scratch fp16: [pixel][c]
__device__ __half g_feat_h[NPX * C];
// W1 in fp16: [c][j]
__device__ __half g_W1h[C * NJ];
// projected features fp16: [pixel][j]
__device__ __half g_proj[NPX * NJ];

// ---------------------------------------------------------------------------
// Kernel 1: temporal mean + NCHW -> NHWC transpose, float4 loads (R11 best).
// grid: (NB*HH, 17), block: 256. cchunk==16 blocks also convert W1 -> fp16.
// ---------------------------------------------------------------------------
__global__ __launch_bounds__(256)
void mean_t_transpose_kernel(const float* __restrict__ x,
                             const float* __restrict__ W1)
{
    __shared__ float tile[32][37];

    const int bid = blockIdx.x;        // b*32 + y
    const int b   = bid >> 5;
    const int y   = bid & 31;
    const int cchunk = blockIdx.y;

    const int tid = threadIdx.x;
    const int xq  = tid & 7;
    const int cl  = tid >> 3;

    const int c = cchunk * 32 + cl;
    if (c < C) {
        const float4* p = (const float4*)
            (x + (((size_t)(b * C + c) * T) * HH + y) * WW + xq * 4);
        float4 s0 = make_float4(0.f, 0.f, 0.f, 0.f);
        float4 s1 = make_float4(0.f, 0.f, 0.f, 0.f);
        #pragma unroll
        for (int t = 0; t < T; t += 2) {
            const float4 v0 = __ldcs(p + (size_t)t       * (HH * WW / 4));
            const float4 v1 = __ldcs(p + (size_t)(t + 1) * (HH * WW / 4));
            s0.x += v0.x; s0.y += v0.y; s0.z += v0.z; s0.w += v0.w;
            s1.x += v1.x; s1.y += v1.y; s1.z += v1.z; s1.w += v1.w;
        }
        const int xb = xq * 4;
        tile[cl][xb + 0] = (s0.x + s1.x) * (1.0f / T);
        tile[cl][xb + 1] = (s0.y + s1.y) * (1.0f / T);
        tile[cl][xb + 2] = (s0.z + s1.z) * (1.0f / T);
        tile[cl][xb + 3] = (s0.w + s1.w) * (1.0f / T);
    }

    if (cchunk == 16) {
        const int base = bid * 264;          // 256 blocks x 264 = 67584
        #pragma unroll
        for (int i = tid; i < 264; i += 256)
            g_W1h[base + i] = __float2half(W1[base + i]);
    }
    __syncthreads();

    const int cw = tid & 31;
    const int xw = tid >> 5;
    const int c2 = cchunk * 32 + cw;
    if (c2 < C) {
        #pragma unroll
        for (int xs = 0; xs < 4; xs++) {
            const int xx = xs * 8 + xw;
            g_feat_h[(((size_t)(b * HH + y)) * WW + xx) * C + c2] =
                __float2half(tile[cw][xx]);
        }
    }
}

// ---------------------------------------------------------------------------
// Kernel 2: projection GEMM proj[8192,128] = feat[8192,528] @ W1h[528,128]
// grid: 256 (32-row tiles), block: 256 (8 warps = 2 warp-rows x 4 warp-cols).
// A tile staged fully in smem (coalesced); B double-buffered 16x128 chunks.
// Epilogue reuses A region for fp32 staging, stores fp16 half2 coalesced.
// ---------------------------------------------------------------------------
#define A_BYTES (32 * C * 2)       // 33792
#define B_BYTES (16 * NJ * 2)      // 4096 per buffer

__global__ __launch_bounds__(256)
void proj_kernel()
{
    __shared__ __align__(16) char smem_raw[A_BYTES + 2 * B_BYTES];
    __half* sA   = (__half*)smem_raw;
    __half* sB   = (__half*)(smem_raw + A_BYTES);
    float*  sOut = (float*)smem_raw;            // reused after k-loop

    const int tid  = threadIdx.x;
    const int wid  = tid >> 5;
    const int wr   = wid & 1;            // warp row (16 rows each)
    const int wc   = wid >> 1;           // warp col (32 cols each)
    const int row0 = blockIdx.x * 32;

    // Stage A tile: 32 rows x 528 halves = 2112 uint4, flat contiguous copy.
    {
        const uint4* Ag = (const uint4*)(g_feat_h + (size_t)row0 * C);
        uint4* As = (uint4*)sA;
        #pragma unroll
        for (int u = tid; u < 2112; u += 256)
            As[u] = Ag[u];
    }

    // Preload B chunk 0 (16x128 halves = 256 uint4, one per thread)
    const uint4* Bg = (const uint4*)g_W1h;
    ((uint4*)sB)[tid] = Bg[tid];
    __syncthreads();

    wmma::fragment<wmma::accumulator, 16, 16, 16, float> acc[2];
    wmma::fill_fragment(acc[0], 0.0f);
    wmma::fill_fragment(acc[1], 0.0f);

    #pragma unroll 1
    for (int s = 0; s < 33; s++) {
        uint4 pre;
        if (s < 32) pre = Bg[(s + 1) * 256 + tid];

        const __half* Bcur = sB + (s & 1) * (16 * NJ);

        wmma::fragment<wmma::matrix_a, 16, 16, 16, __half, wmma::row_major> a;
        wmma::load_matrix_sync(a, sA + (size_t)(wr * 16) * C + s * 16, C);
        #pragma unroll
        for (int i = 0; i < 2; i++) {
            wmma::fragment<wmma::matrix_b, 16, 16, 16, __half, wmma::row_major> bf;
            wmma::load_matrix_sync(bf, Bcur + wc * 32 + i * 16, NJ);
            wmma::mma_sync(acc[i], a, bf, acc[i]);
        }

        if (s < 32)
            ((uint4*)(sB + ((s + 1) & 1) * (16 * NJ)))[tid] = pre;
        __syncthreads();
    }

    // Epilogue: stage fp32 into reused A region, then fp16 half2 stores.
    #pragma unroll
    for (int i = 0; i < 2; i++)
        wmma::store_matrix_sync(sOut + (size_t)(wr * 16) * NJ + wc * 32 + i * 16,
                                acc[i], NJ, wmma::mem_row_major);
    __syncthreads();

    #pragma unroll
    for (int u = tid; u < 32 * 64; u += 256) {
        const int r  = u >> 6;
        const int p2 = u & 63;
        const __half2 h = __floats2half2_rn(sOut[r * NJ + p2 * 2],
                                            sOut[r * NJ + p2 * 2 + 1]);
        ((__half2*)g_proj)[(size_t)(row0 + r) * 64 + p2] = h;
    }
}

// ---------------------------------------------------------------------------
// Kernel 3: ROI pooling in projected 128-dim space + MLP tail. (R15 version)
// grid: R, block: 256 = 16 support-slices x 16 channel-groups.
// ---------------------------------------------------------------------------
__global__ __launch_bounds__(256)
void roi_head_kernel(const float* __restrict__ bbox,
                     const float* __restrict__ b1,
                     const float* __restrict__ W2, const float* __restrict__ b2,
                     const float* __restrict__ W3, const float* __restrict__ b3,
                     float* __restrict__ out)
{
    __shared__ float sAx[32], sAy[32];
    __shared__ int   sB, sXlo, sNx, sYlo, sNy, sN;
    __shared__ int   sOff[MAXSUP];
    __shared__ float sW[MAXSUP];
    __shared__ float sPar[16][16][8];
    __shared__ float sH1[NJ];
    __shared__ float sPart2[4][32];
    __shared__ float sH2[32];

    const int tid = threadIdx.x;
    const int roi = blockIdx.x;

    if (tid < 64) {
        const int axis = tid >> 5;
        const int bin  = tid & 31;
        const float* bb = bbox + roi * 5;
        if (tid == 0) sB = (int)bb[0];

        const float lo_c = bb[1 + axis] * SCALE - 0.5f;
        const float hi_c = bb[3 + axis] * SCALE - 0.5f;
        const float step = (hi_c - lo_c) * (1.0f / (OUTB * SR));

        float w = 0.f;
        #pragma unroll
        for (int s = 0; s < 16; s++) {
            const float v = lo_c + ((float)s + 0.5f) * step;
            const bool valid = (v >= -1.0f) && (v <= 32.0f);
            float vc   = fminf(fmaxf(v, 0.0f), 31.0f);
            float lof  = floorf(vc);
            float frac = vc - lof;
            int ilo = (int)lof;
            int ihi = min(ilo + 1, 31);
            if (valid) {
                if (ilo == bin) w += 1.0f - frac;
                if (ihi == bin) w += frac;
            }
        }
        if (axis) sAy[bin] = w; else sAx[bin] = w;

        unsigned m = __ballot_sync(0xFFFFFFFF, w != 0.f);
        if (bin == 0) {
            int lo, n;
            if (m == 0u) { lo = 0; n = 0; }
            else { lo = __ffs(m) - 1; n = (31 - __clz(m)) - lo + 1; }
            if (axis) { sYlo = lo; sNy = n; }
            else      { sXlo = lo; sNx = n; }
        }
    }
    __syncthreads();

    {
        const int nx = sNx, ny = sNy;
        int n = nx * ny;
        if (n > MAXSUP) n = MAXSUP;
        if (tid == 0) sN = n;
        const int pxbase = sB * (HH * WW);
        for (int i = tid; i < n; i += 256) {
            const int iy = i / nx;
            const int ix = i - iy * nx;
            const int y  = sYlo + iy;
            const int xp = sXlo + ix;
            sOff[i] = (pxbase + y * WW + xp) * (NJ / 8);
            sW[i]   = sAy[y] * sAx[xp] * (1.0f / 256.0f);
        }
    }
    __syncthreads();

    {
        const int lane = tid & 15;
        const int q    = tid >> 4;
        const int n    = sN;
        const uint4* base = (const uint4*)g_proj + lane;

        float a[8];
        #pragma unroll
        for (int s = 0; s < 8; s++) a[s] = 0.f;

        for (int i = q; i < n; i += 16) {
            const float w   = sW[i];
            const uint4 raw = base[sOff[i]];
            const float2 f0 = __half22float2(*(const __half2*)&raw.x);
            const float2 f1 = __half22float2(*(const __half2*)&raw.y);
            const float2 f2 = __half22float2(*(const __half2*)&raw.z);
            const float2 f3 = __half22float2(*(const __half2*)&raw.w);
            a[0] = fmaf(w, f0.x, a[0]); a[1] = fmaf(w, f0.y, a[1]);
            a[2] = fmaf(w, f1.x, a[2]); a[3] = fmaf(w, f1.y, a[3]);
            a[4] = fmaf(w, f2.x, a[4]); a[5] = fmaf(w, f2.y, a[5]);
            a[6] = fmaf(w, f3.x, a[6]); a[7] = fmaf(w, f3.y, a[7]);
        }
        #pragma unroll
        for (int s = 0; s < 8; s++) sPar[q][lane][s] = a[s];
    }
    __syncthreads();

    if (tid < NJ) {
        const int lane = tid >> 3;
        const int sub  = tid & 7;
        float v = 0.f;
        #pragma unroll
        for (int q = 0; q < 16; q++)
            v += sPar[q][lane][sub];
        sH1[tid] = fmaxf(v + b1[tid], 0.f);
    }
    __syncthreads();

    if (tid < 128) {
        const int part = tid >> 5;
        const int j2   = tid & 31;
        const int k0 = part * 32;
        float a0 = 0.f, a1 = 0.f;
        #pragma unroll
        for (int k = k0; k < k0 + 32; k += 2) {
            a0 = fmaf(sH1[k],     W2[(k)     * 32 + j2], a0);
            a1 = fmaf(sH1[k + 1], W2[(k + 1) * 32 + j2], a1);
        }
        sPart2[part][j2] = a0 + a1;
    }
    __syncthreads();
    if (tid < 32) {
        sH2[tid] = (sPart2[0][tid] + sPart2[1][tid])
                 + (sPart2[2][tid] + sPart2[3][tid]) + b2[tid];
    }
    __syncthreads();

    if (tid < 32) {
        float v = sH2[tid] * W3[tid];
        #pragma unroll
        for (int off = 16; off > 0; off >>= 1)
            v += __shfl_xor_sync(0xFFFFFFFF, v, off);
        if (tid == 0)
            out[roi] = 1.0f / (1.0f + expf(-(v + b3[0])));
    }
}

// ---------------------------------------------------------------------------
extern "C" void kernel_launch(void* const* d_in, const int* in_sizes, int n_in,
                              void* d_out, int out_size)
{
    const float* x    = (const float*)d_in[0];
    const float* bbox = (const float*)d_in[1];
    const float* W1   = (const float*)d_in[2];
    const float* b1   = (const float*)d_in[3];
    const float* W2   = (const float*)d_in[4];
    const float* b2   = (const float*)d_in[5];
    const float* W3   = (const float*)d_in[6];
    const float* b3   = (const float*)d_in[7];
    float* out = (float*)d_out;

    dim3 g1(NB * HH, 17);
    mean_t_transpose_kernel<<<g1, 256>>>(x, W1);

    proj_kernel<<<NPX / 32, 256>>>();

    roi_head_kernel<<<R, 256>>>(bbox, b1, W2, b2, W3, b3, out);
}

// round 17
// speedup vs baseline: 1.2294x; 1.2294x over previous
#include <cuda_runtime.h>
#include <cuda_fp16.h>
#include <math.h>

// Problem constants
#define NB    8
#define C     528
#define CV4   (C/4)          // 132 uint2 groups (4 fp16 channels each)
#define T     16
#define HH    32
#define WW    32
#define R     1024
#define OUTB  8
#define SR    2
#define SCALE (1.0f/16.0f)

#define NJ     128
#define MAXSUP 144
#define NQ     4
#define PBLK   544           // 4 gather groups x 136 lanes (132 active)

// NHWC feature scratch fp16: [b][y][x][c]
__device__ __half g_feat_h[NB * HH * WW * C];
// W1 in fp16: [c][j]  (135 KB -- fits L1, enabling inter-block reuse)
__device__ __half g_W1h[C * NJ];

// ---------------------------------------------------------------------------
// Kernel 1: temporal mean + NCHW -> NHWC transpose, float4 loads.
// grid: (NB*HH, 17), block: 256. cchunk==16 blocks also convert W1 -> fp16.
// (R15-measured: 44.4us, 80% DRAM)
// ---------------------------------------------------------------------------
__global__ __launch_bounds__(256)
void mean_t_transpose_kernel(const float* __restrict__ x,
                             const float* __restrict__ W1)
{
    __shared__ float tile[32][37];

    const int bid = blockIdx.x;        // b*32 + y
    const int b   = bid >> 5;
    const int y   = bid & 31;
    const int cchunk = blockIdx.y;

    const int tid = threadIdx.x;
    const int xq  = tid & 7;
    const int cl  = tid >> 3;

    const int c = cchunk * 32 + cl;
    if (c < C) {
        const float4* p = (const float4*)
            (x + (((size_t)(b * C + c) * T) * HH + y) * WW + xq * 4);
        float4 s0 = make_float4(0.f, 0.f, 0.f, 0.f);
        float4 s1 = make_float4(0.f, 0.f, 0.f, 0.f);
        #pragma unroll
        for (int t = 0; t < T; t += 2) {
            const float4 v0 = __ldcs(p + (size_t)t       * (HH * WW / 4));
            const float4 v1 = __ldcs(p + (size_t)(t + 1) * (HH * WW / 4));
            s0.x += v0.x; s0.y += v0.y; s0.z += v0.z; s0.w += v0.w;
            s1.x += v1.x; s1.y += v1.y; s1.z += v1.z; s1.w += v1.w;
        }
        const int xb = xq * 4;
        tile[cl][xb + 0] = (s0.x + s1.x) * (1.0f / T);
        tile[cl][xb + 1] = (s0.y + s1.y) * (1.0f / T);
        tile[cl][xb + 2] = (s0.z + s1.z) * (1.0f / T);
        tile[cl][xb + 3] = (s0.w + s1.w) * (1.0f / T);
    }

    if (cchunk == 16) {
        const int base = bid * 264;          // 256 blocks x 264 = 67584
        #pragma unroll
        for (int i = tid; i < 264; i += 256)
            g_W1h[base + i] = __float2half(W1[base + i]);
    }
    __syncthreads();

    const int cw = tid & 31;
    const int xw = tid >> 5;
    const int c2 = cchunk * 32 + cw;
    if (c2 < C) {
        #pragma unroll
        for (int xs = 0; xs < 4; xs++) {
            const int xx = xs * 8 + xw;
            g_feat_h[(((size_t)(b * HH + y)) * WW + xx) * C + c2] =
                __float2half(tile[cw][xx]);
        }
    }
}

// ---------------------------------------------------------------------------
// Kernel 2: fused ROI pool (R13 4-way split gather) + MLP (fp16 W1 from L1).
// grid: R (one roi per block), block: 544.
// ---------------------------------------------------------------------------
__global__ __launch_bounds__(PBLK)
void roi_fused_kernel(const float* __restrict__ bbox,
                      const float* __restrict__ b1,
                      const float* __restrict__ W2, const float* __restrict__ b2,
                      const float* __restrict__ W3, const float* __restrict__ b3,
                      float* __restrict__ out)
{
    __shared__ float  sAx[32], sAy[32];
    __shared__ int    sB, sXlo, sNx, sYlo, sNy, sN;
    __shared__ int    sOff[MAXSUP];
    __shared__ float  sW[MAXSUP];
    __shared__ float4 sQ[NQ][CV4];        // 8.4 KB
    __shared__ float  sPooled[C];
    __shared__ float  sPart1[8][NJ];      // 4 KB layer-1 partials
    __shared__ float  sH1[NJ];
    __shared__ float  sPart2[4][32];
    __shared__ float  sH2[32];

    const int tid = threadIdx.x;
    const int roi = blockIdx.x;

    // Phase A1: per-bin axis weights (warp0 = x, warp1 = y), deterministic
    if (tid < 64) {
        const int axis = tid >> 5;
        const int bin  = tid & 31;
        const float* bb = bbox + roi * 5;
        if (tid == 0) sB = (int)bb[0];

        const float lo_c = bb[1 + axis] * SCALE - 0.5f;
        const float hi_c = bb[3 + axis] * SCALE - 0.5f;
        const float step = (hi_c - lo_c) * (1.0f / (OUTB * SR));

        float w = 0.f;
        #pragma unroll
        for (int s = 0; s < 16; s++) {
            const float v = lo_c + ((float)s + 0.5f) * step;
            const bool valid = (v >= -1.0f) && (v <= 32.0f);
            float vc   = fminf(fmaxf(v, 0.0f), 31.0f);
            float lof  = floorf(vc);
            float frac = vc - lof;
            int ilo = (int)lof;
            int ihi = min(ilo + 1, 31);
            if (valid) {
                if (ilo == bin) w += 1.0f - frac;
                if (ihi == bin) w += frac;
            }
        }
        if (axis) sAy[bin] = w; else sAx[bin] = w;

        unsigned m = __ballot_sync(0xFFFFFFFF, w != 0.f);
        if (bin == 0) {
            int lo, n;
            if (m == 0u) { lo = 0; n = 0; }
            else { lo = __ffs(m) - 1; n = (31 - __clz(m)) - lo + 1; }
            if (axis) { sYlo = lo; sNy = n; }
            else      { sXlo = lo; sNx = n; }
        }
    }
    __syncthreads();

    // Phase A2: flatten support into (offset, weight) list
    {
        const int nx = sNx, ny = sNy;
        int n = nx * ny;
        if (n > MAXSUP) n = MAXSUP;
        if (tid == 0) sN = n;
        for (int i = tid; i < n; i += PBLK) {
            const int iy = i / nx;
            const int ix = i - iy * nx;
            const int y  = sYlo + iy;
            const int xp = sXlo + ix;
            sOff[i] = (y * WW + xp) * CV4;
            sW[i]   = sAy[y] * sAx[xp] * (1.0f / 256.0f);
        }
    }
    __syncthreads();

    // Phase B: 4-way split gather (R13 proven)
    {
        const int q    = tid / 136;
        const int lane = tid - q * 136;
        if (lane < CV4) {
            const int n  = sN;
            const int nq = (n + NQ - 1) / NQ;
            const int i0 = q * nq;
            const int i1 = min(i0 + nq, n);

            const uint2* base = (const uint2*)g_feat_h
                              + (size_t)sB * (HH * WW * CV4) + lane;

            float4 acc = make_float4(0.f, 0.f, 0.f, 0.f);
            #pragma unroll 4
            for (int i = i0; i < i1; i++) {
                const float w   = sW[i];
                const uint2 raw = base[sOff[i]];
                const float2 f01 = __half22float2(*(const __half2*)&raw.x);
                const float2 f23 = __half22float2(*(const __half2*)&raw.y);
                acc.x = fmaf(w, f01.x, acc.x);
                acc.y = fmaf(w, f01.y, acc.y);
                acc.z = fmaf(w, f23.x, acc.z);
                acc.w = fmaf(w, f23.y, acc.w);
            }
            sQ[q][lane] = acc;
        }
    }
    __syncthreads();

    // Phase B2: deterministic quarter reduction into sPooled
    if (tid < CV4) {
        const float4 a0 = sQ[0][tid];
        const float4 a1 = sQ[1][tid];
        const float4 a2 = sQ[2][tid];
        const float4 a3 = sQ[3][tid];
        float* dst = &sPooled[tid * 4];
        dst[0] = (a0.x + a1.x) + (a2.x + a3.x);
        dst[1] = (a0.y + a1.y) + (a2.y + a3.y);
        dst[2] = (a0.z + a1.z) + (a2.z + a3.z);
        dst[3] = (a0.w + a1.w) + (a2.w + a3.w);
    }
    __syncthreads();

    // Phase C: layer 1 (528 -> 128, relu) using fp16 W1 (L1-resident).
    // 512 threads = 8 c-parts (66 ch each) x 64 half2-j groups.
    if (tid < 512) {
        const int part = tid >> 6;       // 0..7
        const int j2   = tid & 63;       // half2 group over j
        const int c0   = part * 66;
        const __half2* W1h2 = (const __half2*)g_W1h;   // [c][64]

        float a0 = 0.f, a1 = 0.f;
        #pragma unroll 2
        for (int c = c0; c < c0 + 66; c++) {
            const float2 wf = __half22float2(W1h2[c * 64 + j2]);
            const float  p  = sPooled[c];
            a0 = fmaf(p, wf.x, a0);
            a1 = fmaf(p, wf.y, a1);
        }
        sPart1[part][j2 * 2]     = a0;
        sPart1[part][j2 * 2 + 1] = a1;
    }
    __syncthreads();
    if (tid < NJ) {
        float v = ((sPart1[0][tid] + sPart1[1][tid])
                +  (sPart1[2][tid] + sPart1[3][tid]))
                + ((sPart1[4][tid] + sPart1[5][tid])
                +  (sPart1[6][tid] + sPart1[7][tid]));
        sH1[tid] = fmaxf(v + b1[tid], 0.f);
    }
    __syncthreads();

    // Phase D: layer 2 (128 -> 32). 128 threads = 4 k-parts x 32 outputs.
    if (tid < 128) {
        const int part = tid >> 5;
        const int j    = tid & 31;
        const int k0 = part * 32;
        float a0 = 0.f, a1 = 0.f;
        #pragma unroll
        for (int k = k0; k < k0 + 32; k += 2) {
            a0 = fmaf(sH1[k],     W2[(k)     * 32 + j], a0);
            a1 = fmaf(sH1[k + 1], W2[(k + 1) * 32 + j], a1);
        }
        sPart2[part][j] = a0 + a1;
    }
    __syncthreads();
    if (tid < 32) {
        sH2[tid] = (sPart2[0][tid] + sPart2[1][tid])
                 + (sPart2[2][tid] + sPart2[3][tid]) + b2[tid];
    }
    __syncthreads();

    // Phase E: layer 3 + sigmoid (one warp)
    if (tid < 32) {
        float v = sH2[tid] * W3[tid];
        #pragma unroll
        for (int off = 16; off > 0; off >>= 1)
            v += __shfl_xor_sync(0xFFFFFFFF, v, off);
        if (tid == 0)
            out[roi] = 1.0f / (1.0f + expf(-(v + b3[0])));
    }
}

// ---------------------------------------------------------------------------
extern "C" void kernel_launch(void* const* d_in, const int* in_sizes, int n_in,
                              void* d_out, int out_size)
{
    const float* x    = (const float*)d_in[0];
    const float* bbox = (const float*)d_in[1];
    const float* W1   = (const float*)d_in[2];
    const float* b1   = (const float*)d_in[3];
    const float* W2   = (const float*)d_in[4];
    const float* b2   = (const float*)d_in[5];
    const float* W3   = (const float*)d_in[6];
    const float* b3   = (const float*)d_in[7];
    float* out = (float*)d_out;

    dim3 g1(NB * HH, 17);
    mean_t_transpose_kernel<<<g1, 256>>>(x, W1);

    roi_fused_kernel<<<R, PBLK>>>(bbox, b1, W2, b2, W3, b3, out);
}